// round 15
// baseline (speedup 1.0000x reference)
#include <cuda_runtime.h>
#include <cuda_bf16.h>
#include <math.h>

typedef unsigned long long ull;
typedef unsigned int uint;

#define NHEADS 16
#define LOG100F 4.6051701859880914f

// ---------------- scratch (device globals; allocation is forbidden) ----------
// GEMM operand layout: per row of 2048 bf16, 32 blocks of 64; block b =
// [hi(32 bf16 for k in [32b,32b+31]) | lo(32 bf16 same k)]  (128 bytes/block)
__device__ float g_q[512 * 16 * 64 * 64];                 // [bw*16+h][n][d] fp32
__device__ float g_k[512 * 16 * 64 * 64];
__device__ float g_v[512 * 16 * 64 * 64];
__device__ __nv_bfloat16 g_xc[32768 * 2048];              // A for QKV
__device__ __nv_bfloat16 g_oc[32768 * 2048];              // A for OUT
__device__ __nv_bfloat16 g_wc[4 * 1024 * 2048];           // B (per weight row)
__device__ float g_tab[225 * 16];                         // CPB MLP table

__device__ __forceinline__ void mbar_wait(uint addr, uint parity) {
    asm volatile(
        "{\n\t.reg .pred P;\n"
        "WL%=:\n\t"
        "mbarrier.try_wait.parity.shared::cta.b64 P, [%0], %1;\n\t"
        "@P bra WD%=;\n\t"
        "bra WL%=;\n"
        "WD%=:\n\t}"
        :: "r"(addr), "r"(parity) : "memory");
}

// ---------------- CPB MLP: g_tab[225][16] ------------------------------------
__global__ void cpb_kernel(const float* __restrict__ w1, const float* __restrict__ b1,
                           const float* __restrict__ w2) {
    __shared__ float hid[512];
    int p = blockIdx.x;
    int j = threadIdx.x;
    float vh = (float)(p / 15 - 7) * (8.0f / 7.0f);
    float vw = (float)(p % 15 - 7) * (8.0f / 7.0f);
    float t0 = (vh > 0.f ? 1.f : (vh < 0.f ? -1.f : 0.f)) * log2f(fabsf(vh) + 1.0f) * (1.0f / 3.0f);
    float t1 = (vw > 0.f ? 1.f : (vw < 0.f ? -1.f : 0.f)) * log2f(fabsf(vw) + 1.0f) * (1.0f / 3.0f);
    float hv = t0 * w1[j * 2 + 0] + t1 * w1[j * 2 + 1] + b1[j];
    hid[j] = fmaxf(hv, 0.0f);
    __syncthreads();
    if (j < NHEADS) {
        const float* wr = w2 + j * 512;
        float s = 0.f;
        #pragma unroll 8
        for (int q = 0; q < 512; ++q) s += wr[q] * hid[q];
        g_tab[p * NHEADS + j] = s;
    }
}

// ---------------- conversion kernels ------------------------------------------
__device__ __forceinline__ const float* xrow_gather(const float* x, int m) {
    int bw = m >> 6, n = m & 63;
    int b = bw >> 2, wi = bw & 3;
    int hh = (((wi >> 1) << 3) + (n >> 3) + 4) & 15;
    int ww = (((wi & 1) << 3) + (n & 7) + 4) & 15;
    return x + (size_t)(((b << 4) + hh) * 16 + ww) * 1024;
}

__device__ __forceinline__ void split4(float4 v, __nv_bfloat162& h01, __nv_bfloat162& h23,
                                       __nv_bfloat162& l01, __nv_bfloat162& l23) {
    __nv_bfloat16 h0 = __float2bfloat16(v.x), h1 = __float2bfloat16(v.y);
    __nv_bfloat16 h2 = __float2bfloat16(v.z), h3 = __float2bfloat16(v.w);
    __nv_bfloat16 l0 = __float2bfloat16(v.x - __bfloat162float(h0));
    __nv_bfloat16 l1 = __float2bfloat16(v.y - __bfloat162float(h1));
    __nv_bfloat16 l2 = __float2bfloat16(v.z - __bfloat162float(h2));
    __nv_bfloat16 l3 = __float2bfloat16(v.w - __bfloat162float(h3));
    h01.x = h0; h01.y = h1; h23.x = h2; h23.y = h3;
    l01.x = l0; l01.y = l1; l23.x = l2; l23.y = l3;
}

// x -> g_xc with shifted-window gather; interleaved [hi32|lo32] per k32 block
__global__ void conv_x(const float* __restrict__ x) {
    int m = blockIdx.x;
    int t = threadIdx.x;
    const float* src = xrow_gather(x, m);
    float4 v = ((const float4*)src)[t];
    __nv_bfloat162 h01, h23, l01, l23;
    split4(v, h01, h23, l01, l23);
    int b = t >> 3;
    int w = (t & 7) * 4;
    __nv_bfloat16* dst = g_xc + (size_t)m * 2048 + b * 64 + w;
    *(__nv_bfloat162*)(dst)      = h01; *(__nv_bfloat162*)(dst + 2)  = h23;
    *(__nv_bfloat162*)(dst + 32) = l01; *(__nv_bfloat162*)(dst + 34) = l23;
}

// weights -> g_wc; same interleaved layout
__global__ void conv_w(const float* __restrict__ Wq, const float* __restrict__ Wk,
                       const float* __restrict__ Wv, const float* __restrict__ Wo) {
    int j = blockIdx.x;
    int mat = blockIdx.y;
    int t = threadIdx.x;
    const float* W = (mat == 0) ? Wq : (mat == 1) ? Wk : (mat == 2) ? Wv : Wo;
    float4 v = *(const float4*)(W + (size_t)j * 1024 + t * 4);
    __nv_bfloat162 h01, h23, l01, l23;
    split4(v, h01, h23, l01, l23);
    int b = t >> 3;
    int w = (t & 7) * 4;
    __nv_bfloat16* dst = g_wc + ((size_t)mat * 1024 + j) * 2048 + b * 64 + w;
    *(__nv_bfloat162*)(dst)      = h01; *(__nv_bfloat162*)(dst + 2)  = h23;
    *(__nv_bfloat162*)(dst + 32) = l01; *(__nv_bfloat162*)(dst + 34) = l23;
}

// ---------------- common mma helpers ------------------------------------------
__device__ __forceinline__ void ldsm4(uint r[4], uint addr) {
    asm volatile("ldmatrix.sync.aligned.m8n8.x4.shared.b16 {%0,%1,%2,%3}, [%4];"
                 : "=r"(r[0]), "=r"(r[1]), "=r"(r[2]), "=r"(r[3]) : "r"(addr));
}
__device__ __forceinline__ void ldsm4t(uint r[4], uint addr) {
    asm volatile("ldmatrix.sync.aligned.m8n8.x4.trans.shared.b16 {%0,%1,%2,%3}, [%4];"
                 : "=r"(r[0]), "=r"(r[1]), "=r"(r[2]), "=r"(r[3]) : "r"(addr));
}
__device__ __forceinline__ void mma16816(float c[4], const uint a[4], uint b0, uint b1) {
    asm volatile(
        "mma.sync.aligned.m16n8k16.row.col.f32.bf16.bf16.f32 "
        "{%0,%1,%2,%3}, {%4,%5,%6,%7}, {%8,%9}, {%0,%1,%2,%3};"
        : "+f"(c[0]), "+f"(c[1]), "+f"(c[2]), "+f"(c[3])
        : "r"(a[0]), "r"(a[1]), "r"(a[2]), "r"(a[3]), "r"(b0), "r"(b1));
}

// ---------------- mma.sync split-bf16 GEMM ------------------------------------
// R14 mainloop + spread prefetch: empty-wait moved after ks1 term1 (fast path),
// 8 LDGSTS interleaved in 2 groups between remaining mma term blocks to avoid
// MIO/LSU burst contention with the next chunk's ldsm batch.
#define NCH 32
#define STG 32768
#define DYN_SMEM (1024 + 3 * STG)

__global__ __launch_bounds__(256, 2)
void mma_gemm(const __nv_bfloat16* __restrict__ Ag, const __nv_bfloat16* __restrict__ Bg,
              const float* __restrict__ bias, float* __restrict__ outp, int mode) {
    extern __shared__ char dynsm[];
    const int tid = threadIdx.x;
    const int wid = tid >> 5;
    const int lane = tid & 31;
    const int wm = wid >> 1;
    const int wn = wid & 1;
    const int jbase = blockIdx.x * 128;
    const int mbase = blockIdx.y * 128;

    uint smbase = (uint)__cvta_generic_to_shared(dynsm);
    uint tiles = smbase + 1024;
    if (tid == 0) {
        #pragma unroll
        for (int s = 0; s < 3; ++s) {
            asm volatile("mbarrier.init.shared.b64 [%0], 256;" :: "r"(smbase + s * 16) : "memory");
            asm volatile("mbarrier.init.shared.b64 [%0], 8;"   :: "r"(smbase + s * 16 + 8) : "memory");
        }
    }

    const int brow = tid >> 3;
    const int bslot = tid & 7;
    const uint off0 = brow * 128 + ((bslot * 16) ^ ((brow & 7) << 4));
    const uint aoff0 = off0;
    const uint boff0 = 16384 + off0;
    const char* asrc0 = (const char*)(Ag + (size_t)(mbase + brow) * 2048 + bslot * 8);
    const char* bsrc0 = (const char*)(Bg + (size_t)(jbase + brow) * 2048 + bslot * 8);

    auto load_chunk = [&](int c, int s) {
        uint so = tiles + s * STG;
        long gc = (long)c * 128;
        #pragma unroll
        for (int i = 0; i < 4; ++i) {
            asm volatile("cp.async.cg.shared.global [%0], [%1], 16;"
                         :: "r"(so + aoff0 + i * 4096u), "l"(asrc0 + gc + (long)i * 131072));
            asm volatile("cp.async.cg.shared.global [%0], [%1], 16;"
                         :: "r"(so + boff0 + i * 4096u), "l"(bsrc0 + gc + (long)i * 131072));
        }
        asm volatile("cp.async.mbarrier.arrive.noinc.shared::cta.b64 [%0];"
                     :: "r"(smbase + s * 16) : "memory");
    };

    const uint xorv = (lane & 7) << 4;
    const uint hi16 = (lane >> 4) * 16;
    const uint rbA0 = (wm * 32 + (lane & 15)) * 128;
    const uint rbB0 = 16384 + (wn * 64 + (lane & 15)) * 128;

    float acc[2][8][4];
    #pragma unroll
    for (int i = 0; i < 2; ++i)
        #pragma unroll
        for (int j = 0; j < 8; ++j)
            #pragma unroll
            for (int q = 0; q < 4; ++q) acc[i][j][q] = 0.f;

    __syncthreads();

    load_chunk(0, 0);
    load_chunk(1, 1);
    load_chunk(2, 2);

    int s = 0;
    uint ph = 0;
    for (int c = 0; c < NCH; ++c) {
        mbar_wait(smbase + s * 16, ph);
        uint so = tiles + (uint)s * STG;
        const bool pre = (c + 3 < NCH);
        const long gc3 = (long)(c + 3) * 128;

        // ---------------- ks = 0 ----------------
        {
            uint kvh = (0 * 32 + hi16) ^ xorv;
            uint kvl = (64 + 0 * 32 + hi16) ^ xorv;
            uint ahi[2][4], alo[2][4], bh[4][4], bl[4][4];
            ldsm4(ahi[0], so + rbA0 + kvh);
            ldsm4(ahi[1], so + rbA0 + 2048 + kvh);
            ldsm4(alo[0], so + rbA0 + kvl);
            ldsm4(alo[1], so + rbA0 + 2048 + kvl);
            #pragma unroll
            for (int p = 0; p < 4; ++p) ldsm4(bh[p], so + rbB0 + p * 2048 + kvh);
            #pragma unroll
            for (int p = 0; p < 4; ++p) ldsm4(bl[p], so + rbB0 + p * 2048 + kvl);
            #pragma unroll
            for (int mt = 0; mt < 2; ++mt)
                #pragma unroll
                for (int nt = 0; nt < 8; ++nt) {
                    int p = nt >> 1;
                    uint b0 = (nt & 1) ? bh[p][1] : bh[p][0];
                    uint b1 = (nt & 1) ? bh[p][3] : bh[p][2];
                    mma16816(acc[mt][nt], ahi[mt], b0, b1);
                }
            #pragma unroll
            for (int mt = 0; mt < 2; ++mt)
                #pragma unroll
                for (int nt = 0; nt < 8; ++nt) {
                    int p = nt >> 1;
                    uint b0 = (nt & 1) ? bh[p][1] : bh[p][0];
                    uint b1 = (nt & 1) ? bh[p][3] : bh[p][2];
                    mma16816(acc[mt][nt], alo[mt], b0, b1);
                }
            #pragma unroll
            for (int mt = 0; mt < 2; ++mt)
                #pragma unroll
                for (int nt = 0; nt < 8; ++nt) {
                    int p = nt >> 1;
                    uint b0 = (nt & 1) ? bl[p][1] : bl[p][0];
                    uint b1 = (nt & 1) ? bl[p][3] : bl[p][2];
                    mma16816(acc[mt][nt], ahi[mt], b0, b1);
                }
        }
        // ---------------- ks = 1 (prefetch interleaved) ----------------
        {
            uint kvh = (1 * 32 + hi16) ^ xorv;
            uint kvl = (64 + 1 * 32 + hi16) ^ xorv;
            uint ahi[2][4], alo[2][4], bh[4][4], bl[4][4];
            ldsm4(ahi[0], so + rbA0 + kvh);
            ldsm4(ahi[1], so + rbA0 + 2048 + kvh);
            ldsm4(alo[0], so + rbA0 + kvl);
            ldsm4(alo[1], so + rbA0 + 2048 + kvl);
            #pragma unroll
            for (int p = 0; p < 4; ++p) ldsm4(bh[p], so + rbB0 + p * 2048 + kvh);
            #pragma unroll
            for (int p = 0; p < 4; ++p) ldsm4(bl[p], so + rbB0 + p * 2048 + kvl);
            // this warp is done reading slot s: arrive empty now
            if (lane == 0)
                asm volatile("mbarrier.arrive.shared::cta.b64 _, [%0];"
                             :: "r"(smbase + s * 16 + 8) : "memory");
            // term 1
            #pragma unroll
            for (int mt = 0; mt < 2; ++mt)
                #pragma unroll
                for (int nt = 0; nt < 8; ++nt) {
                    int p = nt >> 1;
                    uint b0 = (nt & 1) ? bh[p][1] : bh[p][0];
                    uint b1 = (nt & 1) ? bh[p][3] : bh[p][2];
                    mma16816(acc[mt][nt], ahi[mt], b0, b1);
                }
            // empty-wait here: all warps arrived ~24 HMMA ago -> fast path;
            // 48 HMMA of runway still unissued below.
            if (pre) {
                mbar_wait(smbase + s * 16 + 8, ph);
                // prefetch group 1 (4 LDGSTS)
                #pragma unroll
                for (int i = 0; i < 2; ++i) {
                    asm volatile("cp.async.cg.shared.global [%0], [%1], 16;"
                                 :: "r"(so + aoff0 + i * 4096u), "l"(asrc0 + gc3 + (long)i * 131072));
                    asm volatile("cp.async.cg.shared.global [%0], [%1], 16;"
                                 :: "r"(so + boff0 + i * 4096u), "l"(bsrc0 + gc3 + (long)i * 131072));
                }
            }
            // term 2
            #pragma unroll
            for (int mt = 0; mt < 2; ++mt)
                #pragma unroll
                for (int nt = 0; nt < 8; ++nt) {
                    int p = nt >> 1;
                    uint b0 = (nt & 1) ? bh[p][1] : bh[p][0];
                    uint b1 = (nt & 1) ? bh[p][3] : bh[p][2];
                    mma16816(acc[mt][nt], alo[mt], b0, b1);
                }
            if (pre) {
                // prefetch group 2 (4 LDGSTS) + arrive full
                #pragma unroll
                for (int i = 2; i < 4; ++i) {
                    asm volatile("cp.async.cg.shared.global [%0], [%1], 16;"
                                 :: "r"(so + aoff0 + i * 4096u), "l"(asrc0 + gc3 + (long)i * 131072));
                    asm volatile("cp.async.cg.shared.global [%0], [%1], 16;"
                                 :: "r"(so + boff0 + i * 4096u), "l"(bsrc0 + gc3 + (long)i * 131072));
                }
                asm volatile("cp.async.mbarrier.arrive.noinc.shared::cta.b64 [%0];"
                             :: "r"(smbase + s * 16) : "memory");
            }
            // term 3
            #pragma unroll
            for (int mt = 0; mt < 2; ++mt)
                #pragma unroll
                for (int nt = 0; nt < 8; ++nt) {
                    int p = nt >> 1;
                    uint b0 = (nt & 1) ? bl[p][1] : bl[p][0];
                    uint b1 = (nt & 1) ? bl[p][3] : bl[p][2];
                    mma16816(acc[mt][nt], ahi[mt], b0, b1);
                }
        }
        ++s;
        if (s == 3) { s = 0; ph ^= 1; }
    }

    #pragma unroll
    for (int mt = 0; mt < 2; ++mt) {
        #pragma unroll
        for (int half = 0; half < 2; ++half) {
            int m = mbase + wm * 32 + mt * 16 + (lane >> 2) + half * 8;
            int bw = m >> 6, n = m & 63;
            if (mode == 0) {
                #pragma unroll
                for (int nt = 0; nt < 8; ++nt) {
                    int colg = jbase + wn * 64 + nt * 8 + (lane & 3) * 2;
                    int mat = colg >> 10;
                    int jl = colg & 1023;
                    int head = jl >> 6, dd = jl & 63;
                    float2 v;
                    v.x = acc[mt][nt][half * 2 + 0];
                    v.y = acc[mt][nt][half * 2 + 1];
                    if (mat == 2) { v.x += bias[jl]; v.y += bias[jl + 1]; }
                    float* dst = ((mat == 0) ? g_q : (mat == 1) ? g_k : g_v)
                               + ((size_t)(bw * 16 + head) * 64 + n) * 64 + dd;
                    *(float2*)dst = v;
                }
            } else {
                int b = bw >> 2, wi = bw & 3;
                int hs = ((wi >> 1) << 3) + (n >> 3);
                int ws = ((wi & 1) << 3) + (n & 7);
                int hh = (hs + 4) & 15, ww = (ws + 4) & 15;
                float* orow = outp + ((size_t)((b * 16 + hh) * 16 + ww)) * 1024;
                #pragma unroll
                for (int nt = 0; nt < 8; ++nt) {
                    int colg = jbase + wn * 64 + nt * 8 + (lane & 3) * 2;
                    float2 v;
                    v.x = acc[mt][nt][half * 2 + 0] + bias[colg];
                    v.y = acc[mt][nt][half * 2 + 1] + bias[colg + 1];
                    *(float2*)(orow + colg) = v;
                }
            }
        }
    }
}

// ---------------- attention: tensor-core split-bf16 (R14 state) ---------------
__device__ __forceinline__ int grp(int wi, int n) {
    int hs = ((wi >> 1) << 3) + (n >> 3);
    int ws = ((wi & 1) << 3) + (n & 7);
    int rg = hs < 8 ? 0 : (hs < 12 ? 1 : 2);
    int cg = ws < 8 ? 0 : (ws < 12 ? 1 : 2);
    return rg * 3 + cg;
}

#define AQH 0
#define AQL 8192
#define AKH 16384
#define AKL 24576
#define AVH 32768
#define AVL 40960
#define ASB 49152
#define ANQ 66560
#define ANK 66816
#define ASG 67072
#define ATT_SMEM 68096

__global__ __launch_bounds__(256)
void attn_kernel(const float* __restrict__ logit_scale) {
    extern __shared__ char adsm[];
    float* Sb  = (float*)(adsm + ASB);
    float* nq  = (float*)(adsm + ANQ);
    float* nk  = (float*)(adsm + ANK);
    float* sig = (float*)(adsm + ASG);

    int tid = threadIdx.x;
    int bh = blockIdx.x;
    int bw = bh >> 4;
    int hd = bh & 15;
    int wi = bw & 3;

    const float4* qg = (const float4*)(g_q + (size_t)bh * 4096);
    const float4* kg = (const float4*)(g_k + (size_t)bh * 4096);
    const float4* vg = (const float4*)(g_v + (size_t)bh * 4096);

    #pragma unroll
    for (int r = 0; r < 4; ++r) {
        int idx = tid + 256 * r;
        int row = idx >> 4, c = (idx & 15) * 4;
        uint ad = (uint)(row * 128 + c * 2) ^ ((uint)(row & 7) << 4);
        __nv_bfloat162 h01, h23, l01, l23;
        split4(qg[idx], h01, h23, l01, l23);
        *(__nv_bfloat162*)(adsm + AQH + ad)     = h01;
        *(__nv_bfloat162*)(adsm + AQH + ad + 4) = h23;
        *(__nv_bfloat162*)(adsm + AQL + ad)     = l01;
        *(__nv_bfloat162*)(adsm + AQL + ad + 4) = l23;
        split4(kg[idx], h01, h23, l01, l23);
        *(__nv_bfloat162*)(adsm + AKH + ad)     = h01;
        *(__nv_bfloat162*)(adsm + AKH + ad + 4) = h23;
        *(__nv_bfloat162*)(adsm + AKL + ad)     = l01;
        *(__nv_bfloat162*)(adsm + AKL + ad + 4) = l23;
        split4(vg[idx], h01, h23, l01, l23);
        *(__nv_bfloat162*)(adsm + AVH + ad)     = h01;
        *(__nv_bfloat162*)(adsm + AVH + ad + 4) = h23;
        *(__nv_bfloat162*)(adsm + AVL + ad)     = l01;
        *(__nv_bfloat162*)(adsm + AVL + ad + 4) = l23;
    }
    if (tid < 225) sig[tid] = 16.0f / (1.0f + __expf(-g_tab[tid * NHEADS + hd]));
    __syncthreads();

    {
        int half = tid & 1, row = (tid >> 1) & 63;
        const char* tp = adsm + (tid < 128 ? AQH : AKH);
        const char* tl = tp + 8192;
        float s = 0.f;
        #pragma unroll
        for (int t8 = 0; t8 < 8; ++t8) {
            int cc = half * 32 + t8 * 4;
            uint ad = (uint)(row * 128 + cc * 2) ^ ((uint)(row & 7) << 4);
            float2 a0 = __bfloat1622float2(*(const __nv_bfloat162*)(tp + ad));
            float2 a1 = __bfloat1622float2(*(const __nv_bfloat162*)(tp + ad + 4));
            float2 b0 = __bfloat1622float2(*(const __nv_bfloat162*)(tl + ad));
            float2 b1 = __bfloat1622float2(*(const __nv_bfloat162*)(tl + ad + 4));
            float v0 = a0.x + b0.x, v1 = a0.y + b0.y;
            float v2 = a1.x + b1.x, v3 = a1.y + b1.y;
            s += v0 * v0 + v1 * v1 + v2 * v2 + v3 * v3;
        }
        s += __shfl_xor_sync(0xFFFFFFFFu, s, 1);
        if (!half) {
            float rr = fmaxf(sqrtf(s), 1e-12f);
            if (tid < 128) nq[row] = __expf(fminf(logit_scale[hd], LOG100F)) / rr;
            else           nk[row] = 1.0f / rr;
        }
    }
    __syncthreads();

    uint sb = (uint)__cvta_generic_to_shared(adsm);
    int wid = tid >> 5, lane = tid & 31;
    int wm2 = wid >> 2;
    int wn4 = wid & 3;
    uint xorv = (lane & 7) << 4;
    uint hi16 = (lane >> 4) * 16;
    uint rbA = (wm2 * 32 + (lane & 15)) * 128;
    uint rbB = (wn4 * 16 + (lane & 15)) * 128;

    float acc[2][2][4];
    #pragma unroll
    for (int a = 0; a < 2; ++a)
        #pragma unroll
        for (int b = 0; b < 2; ++b)
            #pragma unroll
            for (int q = 0; q < 4; ++q) acc[a][b][q] = 0.f;

    #pragma unroll
    for (int ks = 0; ks < 4; ++ks) {
        uint kv = (ks * 32 + hi16) ^ xorv;
        uint ah[2][4], al[2][4], bh_[4], bl_[4];
        ldsm4(ah[0], sb + AQH + rbA + kv);
        ldsm4(ah[1], sb + AQH + rbA + 2048 + kv);
        ldsm4(al[0], sb + AQL + rbA + kv);
        ldsm4(al[1], sb + AQL + rbA + 2048 + kv);
        ldsm4(bh_, sb + AKH + rbB + kv);
        ldsm4(bl_, sb + AKL + rbB + kv);
        #pragma unroll
        for (int mt = 0; mt < 2; ++mt)
            #pragma unroll
            for (int nt = 0; nt < 2; ++nt) {
                uint b0 = nt ? bh_[1] : bh_[0];
                uint b1 = nt ? bh_[3] : bh_[2];
                mma16816(acc[mt][nt], ah[mt], b0, b1);
                mma16816(acc[mt][nt], al[mt], b0, b1);
                uint c0 = nt ? bl_[1] : bl_[0];
                uint c1 = nt ? bl_[3] : bl_[2];
                mma16816(acc[mt][nt], ah[mt], c0, c1);
            }
    }

    #pragma unroll
    for (int mt = 0; mt < 2; ++mt)
        #pragma unroll
        for (int half = 0; half < 2; ++half) {
            int i = wm2 * 32 + mt * 16 + (lane >> 2) + half * 8;
            int gi = grp(wi, i);
            int ih = i >> 3, iw = i & 7;
            float sq = nq[i];
            #pragma unroll
            for (int nt = 0; nt < 2; ++nt) {
                int j0 = wn4 * 16 + nt * 8 + (lane & 3) * 2;
                #pragma unroll
                for (int e = 0; e < 2; ++e) {
                    int j = j0 + e;
                    float val;
                    if (grp(wi, j) != gi) {
                        val = -1e30f;
                    } else {
                        int p = (ih - (j >> 3) + 7) * 15 + (iw - (j & 7) + 7);
                        val = acc[mt][nt][half * 2 + e] * sq * nk[j] + sig[p];
                    }
                    Sb[i * 68 + j] = val;
                }
            }
        }
    __syncthreads();

    {
        int r = tid >> 2, q4 = tid & 3;
        float* row = Sb + r * 68 + q4 * 16;
        float mx = -1e30f;
        #pragma unroll
        for (int j = 0; j < 16; ++j) mx = fmaxf(mx, row[j]);
        mx = fmaxf(mx, __shfl_xor_sync(0xFFFFFFFFu, mx, 1));
        mx = fmaxf(mx, __shfl_xor_sync(0xFFFFFFFFu, mx, 2));
        float ss = 0.f;
        #pragma unroll
        for (int j = 0; j < 16; ++j) { float e = __expf(row[j] - mx); row[j] = e; ss += e; }
        ss += __shfl_xor_sync(0xFFFFFFFFu, ss, 1);
        ss += __shfl_xor_sync(0xFFFFFFFFu, ss, 2);
        float inv = 1.0f / ss;
        #pragma unroll
        for (int j = 0; j < 16; ++j) row[j] *= inv;
    }
    __syncthreads();

    #pragma unroll
    for (int r = 0; r < 4; ++r) {
        int idx = tid + 256 * r;
        int row = idx >> 4, c = (idx & 15) * 4;
        float4 pv = *(float4*)(Sb + row * 68 + c);
        __nv_bfloat162 h01, h23, l01, l23;
        split4(pv, h01, h23, l01, l23);
        uint ad = (uint)(row * 128 + c * 2) ^ ((uint)(row & 7) << 4);
        *(__nv_bfloat162*)(adsm + AQH + ad)     = h01;
        *(__nv_bfloat162*)(adsm + AQH + ad + 4) = h23;
        *(__nv_bfloat162*)(adsm + AQL + ad)     = l01;
        *(__nv_bfloat162*)(adsm + AQL + ad + 4) = l23;
    }
    __syncthreads();

    float oac[2][2][4];
    #pragma unroll
    for (int a = 0; a < 2; ++a)
        #pragma unroll
        for (int b = 0; b < 2; ++b)
            #pragma unroll
            for (int q = 0; q < 4; ++q) oac[a][b][q] = 0.f;

    uint vx2 = ((uint)(wn4 * 32 + ((lane >> 4) << 4))) ^ (((uint)(lane & 7)) << 4);
    uint rowb = (lane & 15) * 128;

    #pragma unroll
    for (int ks = 0; ks < 4; ++ks) {
        uint kvq = (ks * 32 + hi16) ^ xorv;
        uint adv = (uint)(ks * 16) * 128 + rowb + vx2;
        uint ph_[2][4], pl_[2][4], vh_[4], vl_[4];
        ldsm4(ph_[0], sb + AQH + rbA + kvq);
        ldsm4(ph_[1], sb + AQH + rbA + 2048 + kvq);
        ldsm4(pl_[0], sb + AQL + rbA + kvq);
        ldsm4(pl_[1], sb + AQL + rbA + 2048 + kvq);
        ldsm4t(vh_, sb + AVH + adv);
        ldsm4t(vl_, sb + AVL + adv);
        #pragma unroll
        for (int mt = 0; mt < 2; ++mt)
            #pragma unroll
            for (int nt = 0; nt < 2; ++nt) {
                uint b0 = nt ? vh_[2] : vh_[0];
                uint b1 = nt ? vh_[3] : vh_[1];
                mma16816(oac[mt][nt], ph_[mt], b0, b1);
                mma16816(oac[mt][nt], pl_[mt], b0, b1);
                uint c0 = nt ? vl_[2] : vl_[0];
                uint c1 = nt ? vl_[3] : vl_[1];
                mma16816(oac[mt][nt], ph_[mt], c0, c1);
            }
    }

    #pragma unroll
    for (int mt = 0; mt < 2; ++mt)
        #pragma unroll
        for (int half = 0; half < 2; ++half) {
            int i = wm2 * 32 + mt * 16 + (lane >> 2) + half * 8;
            __nv_bfloat16* prow = g_oc + (size_t)(bw * 64 + i) * 2048;
            #pragma unroll
            for (int nt = 0; nt < 2; ++nt) {
                int d = wn4 * 16 + nt * 8 + (lane & 3) * 2;
                float x0 = oac[mt][nt][half * 2 + 0];
                float x1 = oac[mt][nt][half * 2 + 1];
                __nv_bfloat16 h0 = __float2bfloat16(x0);
                __nv_bfloat16 h1 = __float2bfloat16(x1);
                __nv_bfloat16 l0 = __float2bfloat16(x0 - __bfloat162float(h0));
                __nv_bfloat16 l1 = __float2bfloat16(x1 - __bfloat162float(h1));
                int cc = hd * 64 + d;
                int blk = cc >> 5, w = cc & 31;
                __nv_bfloat162 hh; hh.x = h0; hh.y = h1;
                __nv_bfloat162 ll; ll.x = l0; ll.y = l1;
                *(__nv_bfloat162*)(prow + blk * 64 + w)      = hh;
                *(__nv_bfloat162*)(prow + blk * 64 + w + 32) = ll;
            }
        }
}

// ---------------- launch ------------------------------------------------------
extern "C" void kernel_launch(void* const* d_in, const int* in_sizes, int n_in,
                              void* d_out, int out_size) {
    const float* x   = (const float*)d_in[0];
    const float* Wq  = (const float*)d_in[1];
    const float* Wk  = (const float*)d_in[2];
    const float* Wv  = (const float*)d_in[3];
    const float* bv  = (const float*)d_in[4];
    const float* Wo  = (const float*)d_in[5];
    const float* bo  = (const float*)d_in[6];
    const float* ls  = (const float*)d_in[7];
    const float* w1  = (const float*)d_in[8];
    const float* b1  = (const float*)d_in[9];
    const float* w2  = (const float*)d_in[10];
    float* out = (float*)d_out;

    cudaFuncSetAttribute(mma_gemm, cudaFuncAttributeMaxDynamicSharedMemorySize, DYN_SMEM);
    cudaFuncSetAttribute(attn_kernel, cudaFuncAttributeMaxDynamicSharedMemorySize, ATT_SMEM);

    cpb_kernel<<<225, 512>>>(w1, b1, w2);
    conv_w<<<dim3(1024, 4), 256>>>(Wq, Wk, Wv, Wo);
    conv_x<<<32768, 256>>>(x);

    __nv_bfloat16* xc = nullptr;
    __nv_bfloat16* oc = nullptr;
    __nv_bfloat16* wc = nullptr;
    cudaGetSymbolAddress((void**)&xc, g_xc);
    cudaGetSymbolAddress((void**)&oc, g_oc);
    cudaGetSymbolAddress((void**)&wc, g_wc);

    // QKV: A = g_xc [32768 x 2048], B = g_wc mats 0-2 (N = 3072)
    mma_gemm<<<dim3(24, 256), 256, DYN_SMEM>>>(xc, wc, bv, nullptr, 0);
    attn_kernel<<<8192, 256, ATT_SMEM>>>(ls);
    // OUT: A = g_oc, B = g_wc mat 3 (N = 1024)
    mma_gemm<<<dim3(8, 256), 256, DYN_SMEM>>>(oc, wc + (size_t)3 * 1024 * 2048, bo, out, 1);
}

// round 16
// speedup vs baseline: 1.0288x; 1.0288x over previous
#include <cuda_runtime.h>
#include <cuda_bf16.h>
#include <math.h>

typedef unsigned long long ull;
typedef unsigned int uint;

#define NHEADS 16
#define LOG100F 4.6051701859880914f

// ---------------- scratch (device globals; allocation is forbidden) ----------
// GEMM operand layout: per row of 2048 bf16, 32 blocks of 64; block b =
// [hi(32 bf16 for k in [32b,32b+31]) | lo(32 bf16 same k)]  (128 bytes/block)
__device__ float g_q[512 * 16 * 64 * 64];                 // [bw*16+h][n][d] fp32
__device__ float g_k[512 * 16 * 64 * 64];
__device__ float g_v[512 * 16 * 64 * 64];
__device__ __nv_bfloat16 g_xc[32768 * 2048];              // A for QKV
__device__ __nv_bfloat16 g_oc[32768 * 2048];              // A for OUT
__device__ __nv_bfloat16 g_wc[4 * 1024 * 2048];           // B (per weight row)
__device__ float g_tab[225 * 16];                         // CPB MLP table

__device__ __forceinline__ void mbar_wait(uint addr, uint parity) {
    asm volatile(
        "{\n\t.reg .pred P;\n"
        "WL%=:\n\t"
        "mbarrier.try_wait.parity.shared::cta.b64 P, [%0], %1;\n\t"
        "@P bra WD%=;\n\t"
        "bra WL%=;\n"
        "WD%=:\n\t}"
        :: "r"(addr), "r"(parity) : "memory");
}

// ---------------- CPB MLP: g_tab[225][16] ------------------------------------
__global__ void cpb_kernel(const float* __restrict__ w1, const float* __restrict__ b1,
                           const float* __restrict__ w2) {
    __shared__ float hid[512];
    int p = blockIdx.x;
    int j = threadIdx.x;
    float vh = (float)(p / 15 - 7) * (8.0f / 7.0f);
    float vw = (float)(p % 15 - 7) * (8.0f / 7.0f);
    float t0 = (vh > 0.f ? 1.f : (vh < 0.f ? -1.f : 0.f)) * log2f(fabsf(vh) + 1.0f) * (1.0f / 3.0f);
    float t1 = (vw > 0.f ? 1.f : (vw < 0.f ? -1.f : 0.f)) * log2f(fabsf(vw) + 1.0f) * (1.0f / 3.0f);
    float hv = t0 * w1[j * 2 + 0] + t1 * w1[j * 2 + 1] + b1[j];
    hid[j] = fmaxf(hv, 0.0f);
    __syncthreads();
    if (j < NHEADS) {
        const float* wr = w2 + j * 512;
        float s = 0.f;
        #pragma unroll 8
        for (int q = 0; q < 512; ++q) s += wr[q] * hid[q];
        g_tab[p * NHEADS + j] = s;
    }
}

// ---------------- conversion kernels ------------------------------------------
__device__ __forceinline__ const float* xrow_gather(const float* x, int m) {
    int bw = m >> 6, n = m & 63;
    int b = bw >> 2, wi = bw & 3;
    int hh = (((wi >> 1) << 3) + (n >> 3) + 4) & 15;
    int ww = (((wi & 1) << 3) + (n & 7) + 4) & 15;
    return x + (size_t)(((b << 4) + hh) * 16 + ww) * 1024;
}

__device__ __forceinline__ void split4(float4 v, __nv_bfloat162& h01, __nv_bfloat162& h23,
                                       __nv_bfloat162& l01, __nv_bfloat162& l23) {
    __nv_bfloat16 h0 = __float2bfloat16(v.x), h1 = __float2bfloat16(v.y);
    __nv_bfloat16 h2 = __float2bfloat16(v.z), h3 = __float2bfloat16(v.w);
    __nv_bfloat16 l0 = __float2bfloat16(v.x - __bfloat162float(h0));
    __nv_bfloat16 l1 = __float2bfloat16(v.y - __bfloat162float(h1));
    __nv_bfloat16 l2 = __float2bfloat16(v.z - __bfloat162float(h2));
    __nv_bfloat16 l3 = __float2bfloat16(v.w - __bfloat162float(h3));
    h01.x = h0; h01.y = h1; h23.x = h2; h23.y = h3;
    l01.x = l0; l01.y = l1; l23.x = l2; l23.y = l3;
}

// x -> g_xc with shifted-window gather; interleaved [hi32|lo32] per k32 block
// grid-stride: 8192 blocks x 256 threads, 2 float4 per thread
__global__ void conv_x(const float* __restrict__ x) {
    int t = threadIdx.x;
    #pragma unroll
    for (int r = 0; r < 2; ++r) {
        int m = blockIdx.x * 2 + r;            // row 0..16383 -> need 32768? no:
        m = blockIdx.x + r * 16384;            // rows split across two halves
        const float* src = xrow_gather(x, m);
        float4 v = ((const float4*)src)[t];
        __nv_bfloat162 h01, h23, l01, l23;
        split4(v, h01, h23, l01, l23);
        int b = t >> 3;
        int w = (t & 7) * 4;
        __nv_bfloat16* dst = g_xc + (size_t)m * 2048 + b * 64 + w;
        *(__nv_bfloat162*)(dst)      = h01; *(__nv_bfloat162*)(dst + 2)  = h23;
        *(__nv_bfloat162*)(dst + 32) = l01; *(__nv_bfloat162*)(dst + 34) = l23;
    }
}

// weights -> g_wc; same interleaved layout
__global__ void conv_w(const float* __restrict__ Wq, const float* __restrict__ Wk,
                       const float* __restrict__ Wv, const float* __restrict__ Wo) {
    int j = blockIdx.x;
    int mat = blockIdx.y;
    int t = threadIdx.x;
    const float* W = (mat == 0) ? Wq : (mat == 1) ? Wk : (mat == 2) ? Wv : Wo;
    float4 v = *(const float4*)(W + (size_t)j * 1024 + t * 4);
    __nv_bfloat162 h01, h23, l01, l23;
    split4(v, h01, h23, l01, l23);
    int b = t >> 3;
    int w = (t & 7) * 4;
    __nv_bfloat16* dst = g_wc + ((size_t)mat * 1024 + j) * 2048 + b * 64 + w;
    *(__nv_bfloat162*)(dst)      = h01; *(__nv_bfloat162*)(dst + 2)  = h23;
    *(__nv_bfloat162*)(dst + 32) = l01; *(__nv_bfloat162*)(dst + 34) = l23;
}

// ---------------- common mma helpers ------------------------------------------
__device__ __forceinline__ void ldsm4(uint r[4], uint addr) {
    asm volatile("ldmatrix.sync.aligned.m8n8.x4.shared.b16 {%0,%1,%2,%3}, [%4];"
                 : "=r"(r[0]), "=r"(r[1]), "=r"(r[2]), "=r"(r[3]) : "r"(addr));
}
__device__ __forceinline__ void ldsm4t(uint r[4], uint addr) {
    asm volatile("ldmatrix.sync.aligned.m8n8.x4.trans.shared.b16 {%0,%1,%2,%3}, [%4];"
                 : "=r"(r[0]), "=r"(r[1]), "=r"(r[2]), "=r"(r[3]) : "r"(addr));
}
__device__ __forceinline__ void mma16816(float c[4], const uint a[4], uint b0, uint b1) {
    asm volatile(
        "mma.sync.aligned.m16n8k16.row.col.f32.bf16.bf16.f32 "
        "{%0,%1,%2,%3}, {%4,%5,%6,%7}, {%8,%9}, {%0,%1,%2,%3};"
        : "+f"(c[0]), "+f"(c[1]), "+f"(c[2]), "+f"(c[3])
        : "r"(a[0]), "r"(a[1]), "r"(a[2]), "r"(a[3]), "r"(b0), "r"(b1));
}

// ---------------- mma.sync split-bf16 GEMM (EXACT R14 mainloop) ----------------
#define NCH 32
#define STG 32768
#define DYN_SMEM (1024 + 3 * STG)

__global__ __launch_bounds__(256, 2)
void mma_gemm(const __nv_bfloat16* __restrict__ Ag, const __nv_bfloat16* __restrict__ Bg,
              const float* __restrict__ bias, float* __restrict__ outp, int mode) {
    extern __shared__ char dynsm[];
    const int tid = threadIdx.x;
    const int wid = tid >> 5;
    const int lane = tid & 31;
    const int wm = wid >> 1;
    const int wn = wid & 1;
    const int jbase = blockIdx.x * 128;
    const int mbase = blockIdx.y * 128;

    uint smbase = (uint)__cvta_generic_to_shared(dynsm);
    uint tiles = smbase + 1024;
    if (tid == 0) {
        #pragma unroll
        for (int s = 0; s < 3; ++s) {
            asm volatile("mbarrier.init.shared.b64 [%0], 256;" :: "r"(smbase + s * 16) : "memory");
            asm volatile("mbarrier.init.shared.b64 [%0], 8;"   :: "r"(smbase + s * 16 + 8) : "memory");
        }
    }

    const int brow = tid >> 3;
    const int bslot = tid & 7;
    const uint off0 = brow * 128 + ((bslot * 16) ^ ((brow & 7) << 4));
    const uint aoff0 = off0;
    const uint boff0 = 16384 + off0;
    const char* asrc0 = (const char*)(Ag + (size_t)(mbase + brow) * 2048 + bslot * 8);
    const char* bsrc0 = (const char*)(Bg + (size_t)(jbase + brow) * 2048 + bslot * 8);

    auto load_chunk = [&](int c, int s) {
        uint so = tiles + s * STG;
        long gc = (long)c * 128;
        #pragma unroll
        for (int i = 0; i < 4; ++i) {
            asm volatile("cp.async.cg.shared.global [%0], [%1], 16;"
                         :: "r"(so + aoff0 + i * 4096u), "l"(asrc0 + gc + (long)i * 131072));
            asm volatile("cp.async.cg.shared.global [%0], [%1], 16;"
                         :: "r"(so + boff0 + i * 4096u), "l"(bsrc0 + gc + (long)i * 131072));
        }
        asm volatile("cp.async.mbarrier.arrive.noinc.shared::cta.b64 [%0];"
                     :: "r"(smbase + s * 16) : "memory");
    };

    const uint xorv = (lane & 7) << 4;
    const uint hi16 = (lane >> 4) * 16;
    const uint rbA0 = (wm * 32 + (lane & 15)) * 128;
    const uint rbB0 = 16384 + (wn * 64 + (lane & 15)) * 128;

    float acc[2][8][4];
    #pragma unroll
    for (int i = 0; i < 2; ++i)
        #pragma unroll
        for (int j = 0; j < 8; ++j)
            #pragma unroll
            for (int q = 0; q < 4; ++q) acc[i][j][q] = 0.f;

    __syncthreads();

    load_chunk(0, 0);
    load_chunk(1, 1);
    load_chunk(2, 2);

    int s = 0;
    uint ph = 0;
    for (int c = 0; c < NCH; ++c) {
        mbar_wait(smbase + s * 16, ph);
        uint so = tiles + (uint)s * STG;

        #pragma unroll
        for (int ks = 0; ks < 2; ++ks) {
            uint kvh = (ks * 32 + hi16) ^ xorv;
            uint kvl = (64 + ks * 32 + hi16) ^ xorv;
            uint ahi[2][4], alo[2][4], bh[4][4], bl[4][4];
            ldsm4(ahi[0], so + rbA0 + kvh);
            ldsm4(ahi[1], so + rbA0 + 2048 + kvh);
            ldsm4(alo[0], so + rbA0 + kvl);
            ldsm4(alo[1], so + rbA0 + 2048 + kvl);
            #pragma unroll
            for (int p = 0; p < 4; ++p) ldsm4(bh[p], so + rbB0 + p * 2048 + kvh);
            #pragma unroll
            for (int p = 0; p < 4; ++p) ldsm4(bl[p], so + rbB0 + p * 2048 + kvl);
            if (ks == 1 && lane == 0)
                asm volatile("mbarrier.arrive.shared::cta.b64 _, [%0];"
                             :: "r"(smbase + s * 16 + 8) : "memory");
            #pragma unroll
            for (int mt = 0; mt < 2; ++mt)
                #pragma unroll
                for (int nt = 0; nt < 8; ++nt) {
                    int p = nt >> 1;
                    uint b0 = (nt & 1) ? bh[p][1] : bh[p][0];
                    uint b1 = (nt & 1) ? bh[p][3] : bh[p][2];
                    mma16816(acc[mt][nt], ahi[mt], b0, b1);
                }
            #pragma unroll
            for (int mt = 0; mt < 2; ++mt)
                #pragma unroll
                for (int nt = 0; nt < 8; ++nt) {
                    int p = nt >> 1;
                    uint b0 = (nt & 1) ? bh[p][1] : bh[p][0];
                    uint b1 = (nt & 1) ? bh[p][3] : bh[p][2];
                    mma16816(acc[mt][nt], alo[mt], b0, b1);
                }
            #pragma unroll
            for (int mt = 0; mt < 2; ++mt)
                #pragma unroll
                for (int nt = 0; nt < 8; ++nt) {
                    int p = nt >> 1;
                    uint b0 = (nt & 1) ? bl[p][1] : bl[p][0];
                    uint b1 = (nt & 1) ? bl[p][3] : bl[p][2];
                    mma16816(acc[mt][nt], ahi[mt], b0, b1);
                }
        }
        if (c + 3 < NCH) {
            mbar_wait(smbase + s * 16 + 8, ph);
            load_chunk(c + 3, s);
        }
        ++s;
        if (s == 3) { s = 0; ph ^= 1; }
    }

    #pragma unroll
    for (int mt = 0; mt < 2; ++mt) {
        #pragma unroll
        for (int half = 0; half < 2; ++half) {
            int m = mbase + wm * 32 + mt * 16 + (lane >> 2) + half * 8;
            int bw = m >> 6, n = m & 63;
            if (mode == 0) {
                #pragma unroll
                for (int nt = 0; nt < 8; ++nt) {
                    int colg = jbase + wn * 64 + nt * 8 + (lane & 3) * 2;
                    int mat = colg >> 10;
                    int jl = colg & 1023;
                    int head = jl >> 6, dd = jl & 63;
                    float2 v;
                    v.x = acc[mt][nt][half * 2 + 0];
                    v.y = acc[mt][nt][half * 2 + 1];
                    if (mat == 2) { v.x += bias[jl]; v.y += bias[jl + 1]; }
                    float* dst = ((mat == 0) ? g_q : (mat == 1) ? g_k : g_v)
                               + ((size_t)(bw * 16 + head) * 64 + n) * 64 + dd;
                    *(float2*)dst = v;
                }
            } else {
                int b = bw >> 2, wi = bw & 3;
                int hs = ((wi >> 1) << 3) + (n >> 3);
                int ws = ((wi & 1) << 3) + (n & 7);
                int hh = (hs + 4) & 15, ww = (ws + 4) & 15;
                float* orow = outp + ((size_t)((b * 16 + hh) * 16 + ww)) * 1024;
                #pragma unroll
                for (int nt = 0; nt < 8; ++nt) {
                    int colg = jbase + wn * 64 + nt * 8 + (lane & 3) * 2;
                    float2 v;
                    v.x = acc[mt][nt][half * 2 + 0] + bias[colg];
                    v.y = acc[mt][nt][half * 2 + 1] + bias[colg + 1];
                    *(float2*)(orow + colg) = v;
                }
            }
        }
    }
}

// ---------------- attention: tensor-core split-bf16 (R14 state) ---------------
__device__ __forceinline__ int grp(int wi, int n) {
    int hs = ((wi >> 1) << 3) + (n >> 3);
    int ws = ((wi & 1) << 3) + (n & 7);
    int rg = hs < 8 ? 0 : (hs < 12 ? 1 : 2);
    int cg = ws < 8 ? 0 : (ws < 12 ? 1 : 2);
    return rg * 3 + cg;
}

#define AQH 0
#define AQL 8192
#define AKH 16384
#define AKL 24576
#define AVH 32768
#define AVL 40960
#define ASB 49152
#define ANQ 66560
#define ANK 66816
#define ASG 67072
#define ATT_SMEM 68096

__global__ __launch_bounds__(256)
void attn_kernel(const float* __restrict__ logit_scale) {
    extern __shared__ char adsm[];
    float* Sb  = (float*)(adsm + ASB);
    float* nq  = (float*)(adsm + ANQ);
    float* nk  = (float*)(adsm + ANK);
    float* sig = (float*)(adsm + ASG);

    int tid = threadIdx.x;
    int bh = blockIdx.x;
    int bw = bh >> 4;
    int hd = bh & 15;
    int wi = bw & 3;

    const float4* qg = (const float4*)(g_q + (size_t)bh * 4096);
    const float4* kg = (const float4*)(g_k + (size_t)bh * 4096);
    const float4* vg = (const float4*)(g_v + (size_t)bh * 4096);

    #pragma unroll
    for (int r = 0; r < 4; ++r) {
        int idx = tid + 256 * r;
        int row = idx >> 4, c = (idx & 15) * 4;
        uint ad = (uint)(row * 128 + c * 2) ^ ((uint)(row & 7) << 4);
        __nv_bfloat162 h01, h23, l01, l23;
        split4(qg[idx], h01, h23, l01, l23);
        *(__nv_bfloat162*)(adsm + AQH + ad)     = h01;
        *(__nv_bfloat162*)(adsm + AQH + ad + 4) = h23;
        *(__nv_bfloat162*)(adsm + AQL + ad)     = l01;
        *(__nv_bfloat162*)(adsm + AQL + ad + 4) = l23;
        split4(kg[idx], h01, h23, l01, l23);
        *(__nv_bfloat162*)(adsm + AKH + ad)     = h01;
        *(__nv_bfloat162*)(adsm + AKH + ad + 4) = h23;
        *(__nv_bfloat162*)(adsm + AKL + ad)     = l01;
        *(__nv_bfloat162*)(adsm + AKL + ad + 4) = l23;
        split4(vg[idx], h01, h23, l01, l23);
        *(__nv_bfloat162*)(adsm + AVH + ad)     = h01;
        *(__nv_bfloat162*)(adsm + AVH + ad + 4) = h23;
        *(__nv_bfloat162*)(adsm + AVL + ad)     = l01;
        *(__nv_bfloat162*)(adsm + AVL + ad + 4) = l23;
    }
    if (tid < 225) sig[tid] = 16.0f / (1.0f + __expf(-g_tab[tid * NHEADS + hd]));
    __syncthreads();

    {
        int half = tid & 1, row = (tid >> 1) & 63;
        const char* tp = adsm + (tid < 128 ? AQH : AKH);
        const char* tl = tp + 8192;
        float s = 0.f;
        #pragma unroll
        for (int t8 = 0; t8 < 8; ++t8) {
            int cc = half * 32 + t8 * 4;
            uint ad = (uint)(row * 128 + cc * 2) ^ ((uint)(row & 7) << 4);
            float2 a0 = __bfloat1622float2(*(const __nv_bfloat162*)(tp + ad));
            float2 a1 = __bfloat1622float2(*(const __nv_bfloat162*)(tp + ad + 4));
            float2 b0 = __bfloat1622float2(*(const __nv_bfloat162*)(tl + ad));
            float2 b1 = __bfloat1622float2(*(const __nv_bfloat162*)(tl + ad + 4));
            float v0 = a0.x + b0.x, v1 = a0.y + b0.y;
            float v2 = a1.x + b1.x, v3 = a1.y + b1.y;
            s += v0 * v0 + v1 * v1 + v2 * v2 + v3 * v3;
        }
        s += __shfl_xor_sync(0xFFFFFFFFu, s, 1);
        if (!half) {
            float rr = fmaxf(sqrtf(s), 1e-12f);
            if (tid < 128) nq[row] = __expf(fminf(logit_scale[hd], LOG100F)) / rr;
            else           nk[row] = 1.0f / rr;
        }
    }
    __syncthreads();

    uint sb = (uint)__cvta_generic_to_shared(adsm);
    int wid = tid >> 5, lane = tid & 31;
    int wm2 = wid >> 2;
    int wn4 = wid & 3;
    uint xorv = (lane & 7) << 4;
    uint hi16 = (lane >> 4) * 16;
    uint rbA = (wm2 * 32 + (lane & 15)) * 128;
    uint rbB = (wn4 * 16 + (lane & 15)) * 128;

    float acc[2][2][4];
    #pragma unroll
    for (int a = 0; a < 2; ++a)
        #pragma unroll
        for (int b = 0; b < 2; ++b)
            #pragma unroll
            for (int q = 0; q < 4; ++q) acc[a][b][q] = 0.f;

    #pragma unroll
    for (int ks = 0; ks < 4; ++ks) {
        uint kv = (ks * 32 + hi16) ^ xorv;
        uint ah[2][4], al[2][4], bh_[4], bl_[4];
        ldsm4(ah[0], sb + AQH + rbA + kv);
        ldsm4(ah[1], sb + AQH + rbA + 2048 + kv);
        ldsm4(al[0], sb + AQL + rbA + kv);
        ldsm4(al[1], sb + AQL + rbA + 2048 + kv);
        ldsm4(bh_, sb + AKH + rbB + kv);
        ldsm4(bl_, sb + AKL + rbB + kv);
        #pragma unroll
        for (int mt = 0; mt < 2; ++mt)
            #pragma unroll
            for (int nt = 0; nt < 2; ++nt) {
                uint b0 = nt ? bh_[1] : bh_[0];
                uint b1 = nt ? bh_[3] : bh_[2];
                mma16816(acc[mt][nt], ah[mt], b0, b1);
                mma16816(acc[mt][nt], al[mt], b0, b1);
                uint c0 = nt ? bl_[1] : bl_[0];
                uint c1 = nt ? bl_[3] : bl_[2];
                mma16816(acc[mt][nt], ah[mt], c0, c1);
            }
    }

    #pragma unroll
    for (int mt = 0; mt < 2; ++mt)
        #pragma unroll
        for (int half = 0; half < 2; ++half) {
            int i = wm2 * 32 + mt * 16 + (lane >> 2) + half * 8;
            int gi = grp(wi, i);
            int ih = i >> 3, iw = i & 7;
            float sq = nq[i];
            #pragma unroll
            for (int nt = 0; nt < 2; ++nt) {
                int j0 = wn4 * 16 + nt * 8 + (lane & 3) * 2;
                #pragma unroll
                for (int e = 0; e < 2; ++e) {
                    int j = j0 + e;
                    float val;
                    if (grp(wi, j) != gi) {
                        val = -1e30f;
                    } else {
                        int p = (ih - (j >> 3) + 7) * 15 + (iw - (j & 7) + 7);
                        val = acc[mt][nt][half * 2 + e] * sq * nk[j] + sig[p];
                    }
                    Sb[i * 68 + j] = val;
                }
            }
        }
    __syncthreads();

    {
        int r = tid >> 2, q4 = tid & 3;
        float* row = Sb + r * 68 + q4 * 16;
        float mx = -1e30f;
        #pragma unroll
        for (int j = 0; j < 16; ++j) mx = fmaxf(mx, row[j]);
        mx = fmaxf(mx, __shfl_xor_sync(0xFFFFFFFFu, mx, 1));
        mx = fmaxf(mx, __shfl_xor_sync(0xFFFFFFFFu, mx, 2));
        float ss = 0.f;
        #pragma unroll
        for (int j = 0; j < 16; ++j) { float e = __expf(row[j] - mx); row[j] = e; ss += e; }
        ss += __shfl_xor_sync(0xFFFFFFFFu, ss, 1);
        ss += __shfl_xor_sync(0xFFFFFFFFu, ss, 2);
        float inv = 1.0f / ss;
        #pragma unroll
        for (int j = 0; j < 16; ++j) row[j] *= inv;
    }
    __syncthreads();

    #pragma unroll
    for (int r = 0; r < 4; ++r) {
        int idx = tid + 256 * r;
        int row = idx >> 4, c = (idx & 15) * 4;
        float4 pv = *(float4*)(Sb + row * 68 + c);
        __nv_bfloat162 h01, h23, l01, l23;
        split4(pv, h01, h23, l01, l23);
        uint ad = (uint)(row * 128 + c * 2) ^ ((uint)(row & 7) << 4);
        *(__nv_bfloat162*)(adsm + AQH + ad)     = h01;
        *(__nv_bfloat162*)(adsm + AQH + ad + 4) = h23;
        *(__nv_bfloat162*)(adsm + AQL + ad)     = l01;
        *(__nv_bfloat162*)(adsm + AQL + ad + 4) = l23;
    }
    __syncthreads();

    float oac[2][2][4];
    #pragma unroll
    for (int a = 0; a < 2; ++a)
        #pragma unroll
        for (int b = 0; b < 2; ++b)
            #pragma unroll
            for (int q = 0; q < 4; ++q) oac[a][b][q] = 0.f;

    uint vx2 = ((uint)(wn4 * 32 + ((lane >> 4) << 4))) ^ (((uint)(lane & 7)) << 4);
    uint rowb = (lane & 15) * 128;

    #pragma unroll
    for (int ks = 0; ks < 4; ++ks) {
        uint kvq = (ks * 32 + hi16) ^ xorv;
        uint adv = (uint)(ks * 16) * 128 + rowb + vx2;
        uint ph_[2][4], pl_[2][4], vh_[4], vl_[4];
        ldsm4(ph_[0], sb + AQH + rbA + kvq);
        ldsm4(ph_[1], sb + AQH + rbA + 2048 + kvq);
        ldsm4(pl_[0], sb + AQL + rbA + kvq);
        ldsm4(pl_[1], sb + AQL + rbA + 2048 + kvq);
        ldsm4t(vh_, sb + AVH + adv);
        ldsm4t(vl_, sb + AVL + adv);
        #pragma unroll
        for (int mt = 0; mt < 2; ++mt)
            #pragma unroll
            for (int nt = 0; nt < 2; ++nt) {
                uint b0 = nt ? vh_[2] : vh_[0];
                uint b1 = nt ? vh_[3] : vh_[1];
                mma16816(oac[mt][nt], ph_[mt], b0, b1);
                mma16816(oac[mt][nt], pl_[mt], b0, b1);
                uint c0 = nt ? vl_[2] : vl_[0];
                uint c1 = nt ? vl_[3] : vl_[1];
                mma16816(oac[mt][nt], ph_[mt], c0, c1);
            }
    }

    #pragma unroll
    for (int mt = 0; mt < 2; ++mt)
        #pragma unroll
        for (int half = 0; half < 2; ++half) {
            int i = wm2 * 32 + mt * 16 + (lane >> 2) + half * 8;
            __nv_bfloat16* prow = g_oc + (size_t)(bw * 64 + i) * 2048;
            #pragma unroll
            for (int nt = 0; nt < 2; ++nt) {
                int d = wn4 * 16 + nt * 8 + (lane & 3) * 2;
                float x0 = oac[mt][nt][half * 2 + 0];
                float x1 = oac[mt][nt][half * 2 + 1];
                __nv_bfloat16 h0 = __float2bfloat16(x0);
                __nv_bfloat16 h1 = __float2bfloat16(x1);
                __nv_bfloat16 l0 = __float2bfloat16(x0 - __bfloat162float(h0));
                __nv_bfloat16 l1 = __float2bfloat16(x1 - __bfloat162float(h1));
                int cc = hd * 64 + d;
                int blk = cc >> 5, w = cc & 31;
                __nv_bfloat162 hh; hh.x = h0; hh.y = h1;
                __nv_bfloat162 ll; ll.x = l0; ll.y = l1;
                *(__nv_bfloat162*)(prow + blk * 64 + w)      = hh;
                *(__nv_bfloat162*)(prow + blk * 64 + w + 32) = ll;
            }
        }
}

// ---------------- launch ------------------------------------------------------
extern "C" void kernel_launch(void* const* d_in, const int* in_sizes, int n_in,
                              void* d_out, int out_size) {
    const float* x   = (const float*)d_in[0];
    const float* Wq  = (const float*)d_in[1];
    const float* Wk  = (const float*)d_in[2];
    const float* Wv  = (const float*)d_in[3];
    const float* bv  = (const float*)d_in[4];
    const float* Wo  = (const float*)d_in[5];
    const float* bo  = (const float*)d_in[6];
    const float* ls  = (const float*)d_in[7];
    const float* w1  = (const float*)d_in[8];
    const float* b1  = (const float*)d_in[9];
    const float* w2  = (const float*)d_in[10];
    float* out = (float*)d_out;

    cudaFuncSetAttribute(mma_gemm, cudaFuncAttributeMaxDynamicSharedMemorySize, DYN_SMEM);
    cudaFuncSetAttribute(attn_kernel, cudaFuncAttributeMaxDynamicSharedMemorySize, ATT_SMEM);

    cpb_kernel<<<225, 512>>>(w1, b1, w2);
    conv_w<<<dim3(1024, 4), 256>>>(Wq, Wk, Wv, Wo);
    conv_x<<<16384, 256>>>(x);

    __nv_bfloat16* xc = nullptr;
    __nv_bfloat16* oc = nullptr;
    __nv_bfloat16* wc = nullptr;
    cudaGetSymbolAddress((void**)&xc, g_xc);
    cudaGetSymbolAddress((void**)&oc, g_oc);
    cudaGetSymbolAddress((void**)&wc, g_wc);

    // QKV: A = g_xc [32768 x 2048], B = g_wc mats 0-2 (N = 3072)
    mma_gemm<<<dim3(24, 256), 256, DYN_SMEM>>>(xc, wc, bv, nullptr, 0);
    attn_kernel<<<8192, 256, ATT_SMEM>>>(ls);
    // OUT: A = g_oc, B = g_wc mat 3 (N = 1024)
    mma_gemm<<<dim3(8, 256), 256, DYN_SMEM>>>(oc, wc + (size_t)3 * 1024 * 2048, bo, out, 1);
}

// round 17
// speedup vs baseline: 1.0319x; 1.0030x over previous
#include <cuda_runtime.h>
#include <cuda_bf16.h>
#include <math.h>

typedef unsigned long long ull;
typedef unsigned int uint;

#define NHEADS 16
#define LOG100F 4.6051701859880914f

// ---------------- scratch (device globals; allocation is forbidden) ----------
// GEMM operand layout: per row of 2048 bf16, 32 blocks of 64; block b =
// [hi(32 bf16 for k in [32b,32b+31]) | lo(32 bf16 same k)]  (128 bytes/block)
__device__ float g_q[512 * 16 * 64 * 64];                 // [bw*16+h][n][d] fp32
__device__ float g_k[512 * 16 * 64 * 64];
__device__ float g_v[512 * 16 * 64 * 64];
__device__ __nv_bfloat16 g_xc[32768 * 2048];              // A for QKV
__device__ __nv_bfloat16 g_oc[32768 * 2048];              // A for OUT
__device__ __nv_bfloat16 g_wc[4 * 1024 * 2048];           // B (per weight row)
__device__ float g_tab[225 * 16];                         // CPB MLP table

__device__ __forceinline__ void mbar_wait(uint addr, uint parity) {
    asm volatile(
        "{\n\t.reg .pred P;\n"
        "WL%=:\n\t"
        "mbarrier.try_wait.parity.shared::cta.b64 P, [%0], %1;\n\t"
        "@P bra WD%=;\n\t"
        "bra WL%=;\n"
        "WD%=:\n\t}"
        :: "r"(addr), "r"(parity) : "memory");
}

// ---------------- helpers ------------------------------------------------------
__device__ __forceinline__ const float* xrow_gather(const float* x, int m) {
    int bw = m >> 6, n = m & 63;
    int b = bw >> 2, wi = bw & 3;
    int hh = (((wi >> 1) << 3) + (n >> 3) + 4) & 15;
    int ww = (((wi & 1) << 3) + (n & 7) + 4) & 15;
    return x + (size_t)(((b << 4) + hh) * 16 + ww) * 1024;
}

__device__ __forceinline__ void split4(float4 v, __nv_bfloat162& h01, __nv_bfloat162& h23,
                                       __nv_bfloat162& l01, __nv_bfloat162& l23) {
    __nv_bfloat16 h0 = __float2bfloat16(v.x), h1 = __float2bfloat16(v.y);
    __nv_bfloat16 h2 = __float2bfloat16(v.z), h3 = __float2bfloat16(v.w);
    __nv_bfloat16 l0 = __float2bfloat16(v.x - __bfloat162float(h0));
    __nv_bfloat16 l1 = __float2bfloat16(v.y - __bfloat162float(h1));
    __nv_bfloat16 l2 = __float2bfloat16(v.z - __bfloat162float(h2));
    __nv_bfloat16 l3 = __float2bfloat16(v.w - __bfloat162float(h3));
    h01.x = h0; h01.y = h1; h23.x = h2; h23.y = h3;
    l01.x = l0; l01.y = l1; l23.x = l2; l23.y = l3;
}

// ---------------- fused prologue: conv_x + conv_w + cpb ------------------------
// blocks [0,16384): conv_x rows blockIdx.x and blockIdx.x+16384
// blocks [16384,20480): conv_w row (idx&1023) of matrix (idx>>10)
// blocks [20480,20705): cpb position p = idx (256 threads, 2 hidden units each)
__global__ void fused_pre(const float* __restrict__ x,
                          const float* __restrict__ Wq, const float* __restrict__ Wk,
                          const float* __restrict__ Wv, const float* __restrict__ Wo,
                          const float* __restrict__ w1, const float* __restrict__ b1,
                          const float* __restrict__ w2) {
    int t = threadIdx.x;
    int bid = blockIdx.x;
    if (bid < 16384) {
        #pragma unroll
        for (int r = 0; r < 2; ++r) {
            int m = bid + r * 16384;
            const float* src = xrow_gather(x, m);
            float4 v = ((const float4*)src)[t];
            __nv_bfloat162 h01, h23, l01, l23;
            split4(v, h01, h23, l01, l23);
            int b = t >> 3;
            int w = (t & 7) * 4;
            __nv_bfloat16* dst = g_xc + (size_t)m * 2048 + b * 64 + w;
            *(__nv_bfloat162*)(dst)      = h01; *(__nv_bfloat162*)(dst + 2)  = h23;
            *(__nv_bfloat162*)(dst + 32) = l01; *(__nv_bfloat162*)(dst + 34) = l23;
        }
    } else if (bid < 20480) {
        int idx = bid - 16384;
        int j = idx & 1023;
        int mat = idx >> 10;
        const float* W = (mat == 0) ? Wq : (mat == 1) ? Wk : (mat == 2) ? Wv : Wo;
        float4 v = *(const float4*)(W + (size_t)j * 1024 + t * 4);
        __nv_bfloat162 h01, h23, l01, l23;
        split4(v, h01, h23, l01, l23);
        int b = t >> 3;
        int w = (t & 7) * 4;
        __nv_bfloat16* dst = g_wc + ((size_t)mat * 1024 + j) * 2048 + b * 64 + w;
        *(__nv_bfloat162*)(dst)      = h01; *(__nv_bfloat162*)(dst + 2)  = h23;
        *(__nv_bfloat162*)(dst + 32) = l01; *(__nv_bfloat162*)(dst + 34) = l23;
    } else {
        __shared__ float hid[512];
        int p = bid - 20480;
        float vh = (float)(p / 15 - 7) * (8.0f / 7.0f);
        float vw = (float)(p % 15 - 7) * (8.0f / 7.0f);
        float t0 = (vh > 0.f ? 1.f : (vh < 0.f ? -1.f : 0.f)) * log2f(fabsf(vh) + 1.0f) * (1.0f / 3.0f);
        float t1 = (vw > 0.f ? 1.f : (vw < 0.f ? -1.f : 0.f)) * log2f(fabsf(vw) + 1.0f) * (1.0f / 3.0f);
        #pragma unroll
        for (int r = 0; r < 2; ++r) {
            int j = t + r * 256;
            float hv = t0 * w1[j * 2 + 0] + t1 * w1[j * 2 + 1] + b1[j];
            hid[j] = fmaxf(hv, 0.0f);
        }
        __syncthreads();
        if (t < NHEADS) {
            const float* wr = w2 + t * 512;
            float s = 0.f;
            #pragma unroll 8
            for (int q = 0; q < 512; ++q) s += wr[q] * hid[q];
            g_tab[p * NHEADS + t] = s;
        }
    }
}

// ---------------- common mma helpers ------------------------------------------
__device__ __forceinline__ void ldsm4(uint r[4], uint addr) {
    asm volatile("ldmatrix.sync.aligned.m8n8.x4.shared.b16 {%0,%1,%2,%3}, [%4];"
                 : "=r"(r[0]), "=r"(r[1]), "=r"(r[2]), "=r"(r[3]) : "r"(addr));
}
__device__ __forceinline__ void ldsm4t(uint r[4], uint addr) {
    asm volatile("ldmatrix.sync.aligned.m8n8.x4.trans.shared.b16 {%0,%1,%2,%3}, [%4];"
                 : "=r"(r[0]), "=r"(r[1]), "=r"(r[2]), "=r"(r[3]) : "r"(addr));
}
__device__ __forceinline__ void mma16816(float c[4], const uint a[4], uint b0, uint b1) {
    asm volatile(
        "mma.sync.aligned.m16n8k16.row.col.f32.bf16.bf16.f32 "
        "{%0,%1,%2,%3}, {%4,%5,%6,%7}, {%8,%9}, {%0,%1,%2,%3};"
        : "+f"(c[0]), "+f"(c[1]), "+f"(c[2]), "+f"(c[3])
        : "r"(a[0]), "r"(a[1]), "r"(a[2]), "r"(a[3]), "r"(b0), "r"(b1));
}

// ---------------- mma.sync split-bf16 GEMM (EXACT R14/R16 mainloop) ------------
#define NCH 32
#define STG 32768
#define DYN_SMEM (1024 + 3 * STG)

__global__ __launch_bounds__(256, 2)
void mma_gemm(const __nv_bfloat16* __restrict__ Ag, const __nv_bfloat16* __restrict__ Bg,
              const float* __restrict__ bias, float* __restrict__ outp, int mode) {
    extern __shared__ char dynsm[];
    const int tid = threadIdx.x;
    const int wid = tid >> 5;
    const int lane = tid & 31;
    const int wm = wid >> 1;
    const int wn = wid & 1;
    const int jbase = blockIdx.x * 128;
    const int mbase = blockIdx.y * 128;

    uint smbase = (uint)__cvta_generic_to_shared(dynsm);
    uint tiles = smbase + 1024;
    if (tid == 0) {
        #pragma unroll
        for (int s = 0; s < 3; ++s) {
            asm volatile("mbarrier.init.shared.b64 [%0], 256;" :: "r"(smbase + s * 16) : "memory");
            asm volatile("mbarrier.init.shared.b64 [%0], 8;"   :: "r"(smbase + s * 16 + 8) : "memory");
        }
    }

    const int brow = tid >> 3;
    const int bslot = tid & 7;
    const uint off0 = brow * 128 + ((bslot * 16) ^ ((brow & 7) << 4));
    const uint aoff0 = off0;
    const uint boff0 = 16384 + off0;
    const char* asrc0 = (const char*)(Ag + (size_t)(mbase + brow) * 2048 + bslot * 8);
    const char* bsrc0 = (const char*)(Bg + (size_t)(jbase + brow) * 2048 + bslot * 8);

    auto load_chunk = [&](int c, int s) {
        uint so = tiles + s * STG;
        long gc = (long)c * 128;
        #pragma unroll
        for (int i = 0; i < 4; ++i) {
            asm volatile("cp.async.cg.shared.global [%0], [%1], 16;"
                         :: "r"(so + aoff0 + i * 4096u), "l"(asrc0 + gc + (long)i * 131072));
            asm volatile("cp.async.cg.shared.global [%0], [%1], 16;"
                         :: "r"(so + boff0 + i * 4096u), "l"(bsrc0 + gc + (long)i * 131072));
        }
        asm volatile("cp.async.mbarrier.arrive.noinc.shared::cta.b64 [%0];"
                     :: "r"(smbase + s * 16) : "memory");
    };

    const uint xorv = (lane & 7) << 4;
    const uint hi16 = (lane >> 4) * 16;
    const uint rbA0 = (wm * 32 + (lane & 15)) * 128;
    const uint rbB0 = 16384 + (wn * 64 + (lane & 15)) * 128;

    float acc[2][8][4];
    #pragma unroll
    for (int i = 0; i < 2; ++i)
        #pragma unroll
        for (int j = 0; j < 8; ++j)
            #pragma unroll
            for (int q = 0; q < 4; ++q) acc[i][j][q] = 0.f;

    __syncthreads();

    load_chunk(0, 0);
    load_chunk(1, 1);
    load_chunk(2, 2);

    int s = 0;
    uint ph = 0;
    for (int c = 0; c < NCH; ++c) {
        mbar_wait(smbase + s * 16, ph);
        uint so = tiles + (uint)s * STG;

        #pragma unroll
        for (int ks = 0; ks < 2; ++ks) {
            uint kvh = (ks * 32 + hi16) ^ xorv;
            uint kvl = (64 + ks * 32 + hi16) ^ xorv;
            uint ahi[2][4], alo[2][4], bh[4][4], bl[4][4];
            ldsm4(ahi[0], so + rbA0 + kvh);
            ldsm4(ahi[1], so + rbA0 + 2048 + kvh);
            ldsm4(alo[0], so + rbA0 + kvl);
            ldsm4(alo[1], so + rbA0 + 2048 + kvl);
            #pragma unroll
            for (int p = 0; p < 4; ++p) ldsm4(bh[p], so + rbB0 + p * 2048 + kvh);
            #pragma unroll
            for (int p = 0; p < 4; ++p) ldsm4(bl[p], so + rbB0 + p * 2048 + kvl);
            if (ks == 1 && lane == 0)
                asm volatile("mbarrier.arrive.shared::cta.b64 _, [%0];"
                             :: "r"(smbase + s * 16 + 8) : "memory");
            #pragma unroll
            for (int mt = 0; mt < 2; ++mt)
                #pragma unroll
                for (int nt = 0; nt < 8; ++nt) {
                    int p = nt >> 1;
                    uint b0 = (nt & 1) ? bh[p][1] : bh[p][0];
                    uint b1 = (nt & 1) ? bh[p][3] : bh[p][2];
                    mma16816(acc[mt][nt], ahi[mt], b0, b1);
                }
            #pragma unroll
            for (int mt = 0; mt < 2; ++mt)
                #pragma unroll
                for (int nt = 0; nt < 8; ++nt) {
                    int p = nt >> 1;
                    uint b0 = (nt & 1) ? bh[p][1] : bh[p][0];
                    uint b1 = (nt & 1) ? bh[p][3] : bh[p][2];
                    mma16816(acc[mt][nt], alo[mt], b0, b1);
                }
            #pragma unroll
            for (int mt = 0; mt < 2; ++mt)
                #pragma unroll
                for (int nt = 0; nt < 8; ++nt) {
                    int p = nt >> 1;
                    uint b0 = (nt & 1) ? bl[p][1] : bl[p][0];
                    uint b1 = (nt & 1) ? bl[p][3] : bl[p][2];
                    mma16816(acc[mt][nt], ahi[mt], b0, b1);
                }
        }
        if (c + 3 < NCH) {
            mbar_wait(smbase + s * 16 + 8, ph);
            load_chunk(c + 3, s);
        }
        ++s;
        if (s == 3) { s = 0; ph ^= 1; }
    }

    #pragma unroll
    for (int mt = 0; mt < 2; ++mt) {
        #pragma unroll
        for (int half = 0; half < 2; ++half) {
            int m = mbase + wm * 32 + mt * 16 + (lane >> 2) + half * 8;
            int bw = m >> 6, n = m & 63;
            if (mode == 0) {
                #pragma unroll
                for (int nt = 0; nt < 8; ++nt) {
                    int colg = jbase + wn * 64 + nt * 8 + (lane & 3) * 2;
                    int mat = colg >> 10;
                    int jl = colg & 1023;
                    int head = jl >> 6, dd = jl & 63;
                    float2 v;
                    v.x = acc[mt][nt][half * 2 + 0];
                    v.y = acc[mt][nt][half * 2 + 1];
                    if (mat == 2) { v.x += bias[jl]; v.y += bias[jl + 1]; }
                    float* dst = ((mat == 0) ? g_q : (mat == 1) ? g_k : g_v)
                               + ((size_t)(bw * 16 + head) * 64 + n) * 64 + dd;
                    *(float2*)dst = v;
                }
            } else {
                int b = bw >> 2, wi = bw & 3;
                int hs = ((wi >> 1) << 3) + (n >> 3);
                int ws = ((wi & 1) << 3) + (n & 7);
                int hh = (hs + 4) & 15, ww = (ws + 4) & 15;
                float* orow = outp + ((size_t)((b * 16 + hh) * 16 + ww)) * 1024;
                #pragma unroll
                for (int nt = 0; nt < 8; ++nt) {
                    int colg = jbase + wn * 64 + nt * 8 + (lane & 3) * 2;
                    float2 v;
                    v.x = acc[mt][nt][half * 2 + 0] + bias[colg];
                    v.y = acc[mt][nt][half * 2 + 1] + bias[colg + 1];
                    *(float2*)(orow + colg) = v;
                }
            }
        }
    }
}

// ---------------- attention: tensor-core split-bf16 (R14/R16 state) ------------
__device__ __forceinline__ int grp(int wi, int n) {
    int hs = ((wi >> 1) << 3) + (n >> 3);
    int ws = ((wi & 1) << 3) + (n & 7);
    int rg = hs < 8 ? 0 : (hs < 12 ? 1 : 2);
    int cg = ws < 8 ? 0 : (ws < 12 ? 1 : 2);
    return rg * 3 + cg;
}

#define AQH 0
#define AQL 8192
#define AKH 16384
#define AKL 24576
#define AVH 32768
#define AVL 40960
#define ASB 49152
#define ANQ 66560
#define ANK 66816
#define ASG 67072
#define ATT_SMEM 68096

__global__ __launch_bounds__(256)
void attn_kernel(const float* __restrict__ logit_scale) {
    extern __shared__ char adsm[];
    float* Sb  = (float*)(adsm + ASB);
    float* nq  = (float*)(adsm + ANQ);
    float* nk  = (float*)(adsm + ANK);
    float* sig = (float*)(adsm + ASG);

    int tid = threadIdx.x;
    int bh = blockIdx.x;
    int bw = bh >> 4;
    int hd = bh & 15;
    int wi = bw & 3;

    const float4* qg = (const float4*)(g_q + (size_t)bh * 4096);
    const float4* kg = (const float4*)(g_k + (size_t)bh * 4096);
    const float4* vg = (const float4*)(g_v + (size_t)bh * 4096);

    #pragma unroll
    for (int r = 0; r < 4; ++r) {
        int idx = tid + 256 * r;
        int row = idx >> 4, c = (idx & 15) * 4;
        uint ad = (uint)(row * 128 + c * 2) ^ ((uint)(row & 7) << 4);
        __nv_bfloat162 h01, h23, l01, l23;
        split4(qg[idx], h01, h23, l01, l23);
        *(__nv_bfloat162*)(adsm + AQH + ad)     = h01;
        *(__nv_bfloat162*)(adsm + AQH + ad + 4) = h23;
        *(__nv_bfloat162*)(adsm + AQL + ad)     = l01;
        *(__nv_bfloat162*)(adsm + AQL + ad + 4) = l23;
        split4(kg[idx], h01, h23, l01, l23);
        *(__nv_bfloat162*)(adsm + AKH + ad)     = h01;
        *(__nv_bfloat162*)(adsm + AKH + ad + 4) = h23;
        *(__nv_bfloat162*)(adsm + AKL + ad)     = l01;
        *(__nv_bfloat162*)(adsm + AKL + ad + 4) = l23;
        split4(vg[idx], h01, h23, l01, l23);
        *(__nv_bfloat162*)(adsm + AVH + ad)     = h01;
        *(__nv_bfloat162*)(adsm + AVH + ad + 4) = h23;
        *(__nv_bfloat162*)(adsm + AVL + ad)     = l01;
        *(__nv_bfloat162*)(adsm + AVL + ad + 4) = l23;
    }
    if (tid < 225) sig[tid] = 16.0f / (1.0f + __expf(-g_tab[tid * NHEADS + hd]));
    __syncthreads();

    {
        int half = tid & 1, row = (tid >> 1) & 63;
        const char* tp = adsm + (tid < 128 ? AQH : AKH);
        const char* tl = tp + 8192;
        float s = 0.f;
        #pragma unroll
        for (int t8 = 0; t8 < 8; ++t8) {
            int cc = half * 32 + t8 * 4;
            uint ad = (uint)(row * 128 + cc * 2) ^ ((uint)(row & 7) << 4);
            float2 a0 = __bfloat1622float2(*(const __nv_bfloat162*)(tp + ad));
            float2 a1 = __bfloat1622float2(*(const __nv_bfloat162*)(tp + ad + 4));
            float2 b0 = __bfloat1622float2(*(const __nv_bfloat162*)(tl + ad));
            float2 b1 = __bfloat1622float2(*(const __nv_bfloat162*)(tl + ad + 4));
            float v0 = a0.x + b0.x, v1 = a0.y + b0.y;
            float v2 = a1.x + b1.x, v3 = a1.y + b1.y;
            s += v0 * v0 + v1 * v1 + v2 * v2 + v3 * v3;
        }
        s += __shfl_xor_sync(0xFFFFFFFFu, s, 1);
        if (!half) {
            float rr = fmaxf(sqrtf(s), 1e-12f);
            if (tid < 128) nq[row] = __expf(fminf(logit_scale[hd], LOG100F)) / rr;
            else           nk[row] = 1.0f / rr;
        }
    }
    __syncthreads();

    uint sb = (uint)__cvta_generic_to_shared(adsm);
    int wid = tid >> 5, lane = tid & 31;
    int wm2 = wid >> 2;
    int wn4 = wid & 3;
    uint xorv = (lane & 7) << 4;
    uint hi16 = (lane >> 4) * 16;
    uint rbA = (wm2 * 32 + (lane & 15)) * 128;
    uint rbB = (wn4 * 16 + (lane & 15)) * 128;

    float acc[2][2][4];
    #pragma unroll
    for (int a = 0; a < 2; ++a)
        #pragma unroll
        for (int b = 0; b < 2; ++b)
            #pragma unroll
            for (int q = 0; q < 4; ++q) acc[a][b][q] = 0.f;

    #pragma unroll
    for (int ks = 0; ks < 4; ++ks) {
        uint kv = (ks * 32 + hi16) ^ xorv;
        uint ah[2][4], al[2][4], bh_[4], bl_[4];
        ldsm4(ah[0], sb + AQH + rbA + kv);
        ldsm4(ah[1], sb + AQH + rbA + 2048 + kv);
        ldsm4(al[0], sb + AQL + rbA + kv);
        ldsm4(al[1], sb + AQL + rbA + 2048 + kv);
        ldsm4(bh_, sb + AKH + rbB + kv);
        ldsm4(bl_, sb + AKL + rbB + kv);
        #pragma unroll
        for (int mt = 0; mt < 2; ++mt)
            #pragma unroll
            for (int nt = 0; nt < 2; ++nt) {
                uint b0 = nt ? bh_[1] : bh_[0];
                uint b1 = nt ? bh_[3] : bh_[2];
                mma16816(acc[mt][nt], ah[mt], b0, b1);
                mma16816(acc[mt][nt], al[mt], b0, b1);
                uint c0 = nt ? bl_[1] : bl_[0];
                uint c1 = nt ? bl_[3] : bl_[2];
                mma16816(acc[mt][nt], ah[mt], c0, c1);
            }
    }

    #pragma unroll
    for (int mt = 0; mt < 2; ++mt)
        #pragma unroll
        for (int half = 0; half < 2; ++half) {
            int i = wm2 * 32 + mt * 16 + (lane >> 2) + half * 8;
            int gi = grp(wi, i);
            int ih = i >> 3, iw = i & 7;
            float sq = nq[i];
            #pragma unroll
            for (int nt = 0; nt < 2; ++nt) {
                int j0 = wn4 * 16 + nt * 8 + (lane & 3) * 2;
                #pragma unroll
                for (int e = 0; e < 2; ++e) {
                    int j = j0 + e;
                    float val;
                    if (grp(wi, j) != gi) {
                        val = -1e30f;
                    } else {
                        int p = (ih - (j >> 3) + 7) * 15 + (iw - (j & 7) + 7);
                        val = acc[mt][nt][half * 2 + e] * sq * nk[j] + sig[p];
                    }
                    Sb[i * 68 + j] = val;
                }
            }
        }
    __syncthreads();

    {
        int r = tid >> 2, q4 = tid & 3;
        float* row = Sb + r * 68 + q4 * 16;
        float mx = -1e30f;
        #pragma unroll
        for (int j = 0; j < 16; ++j) mx = fmaxf(mx, row[j]);
        mx = fmaxf(mx, __shfl_xor_sync(0xFFFFFFFFu, mx, 1));
        mx = fmaxf(mx, __shfl_xor_sync(0xFFFFFFFFu, mx, 2));
        float ss = 0.f;
        #pragma unroll
        for (int j = 0; j < 16; ++j) { float e = __expf(row[j] - mx); row[j] = e; ss += e; }
        ss += __shfl_xor_sync(0xFFFFFFFFu, ss, 1);
        ss += __shfl_xor_sync(0xFFFFFFFFu, ss, 2);
        float inv = 1.0f / ss;
        #pragma unroll
        for (int j = 0; j < 16; ++j) row[j] *= inv;
    }
    __syncthreads();

    #pragma unroll
    for (int r = 0; r < 4; ++r) {
        int idx = tid + 256 * r;
        int row = idx >> 4, c = (idx & 15) * 4;
        float4 pv = *(float4*)(Sb + row * 68 + c);
        __nv_bfloat162 h01, h23, l01, l23;
        split4(pv, h01, h23, l01, l23);
        uint ad = (uint)(row * 128 + c * 2) ^ ((uint)(row & 7) << 4);
        *(__nv_bfloat162*)(adsm + AQH + ad)     = h01;
        *(__nv_bfloat162*)(adsm + AQH + ad + 4) = h23;
        *(__nv_bfloat162*)(adsm + AQL + ad)     = l01;
        *(__nv_bfloat162*)(adsm + AQL + ad + 4) = l23;
    }
    __syncthreads();

    float oac[2][2][4];
    #pragma unroll
    for (int a = 0; a < 2; ++a)
        #pragma unroll
        for (int b = 0; b < 2; ++b)
            #pragma unroll
            for (int q = 0; q < 4; ++q) oac[a][b][q] = 0.f;

    uint vx2 = ((uint)(wn4 * 32 + ((lane >> 4) << 4))) ^ (((uint)(lane & 7)) << 4);
    uint rowb = (lane & 15) * 128;

    #pragma unroll
    for (int ks = 0; ks < 4; ++ks) {
        uint kvq = (ks * 32 + hi16) ^ xorv;
        uint adv = (uint)(ks * 16) * 128 + rowb + vx2;
        uint ph_[2][4], pl_[2][4], vh_[4], vl_[4];
        ldsm4(ph_[0], sb + AQH + rbA + kvq);
        ldsm4(ph_[1], sb + AQH + rbA + 2048 + kvq);
        ldsm4(pl_[0], sb + AQL + rbA + kvq);
        ldsm4(pl_[1], sb + AQL + rbA + 2048 + kvq);
        ldsm4t(vh_, sb + AVH + adv);
        ldsm4t(vl_, sb + AVL + adv);
        #pragma unroll
        for (int mt = 0; mt < 2; ++mt)
            #pragma unroll
            for (int nt = 0; nt < 2; ++nt) {
                uint b0 = nt ? vh_[2] : vh_[0];
                uint b1 = nt ? vh_[3] : vh_[1];
                mma16816(oac[mt][nt], ph_[mt], b0, b1);
                mma16816(oac[mt][nt], pl_[mt], b0, b1);
                uint c0 = nt ? vl_[2] : vl_[0];
                uint c1 = nt ? vl_[3] : vl_[1];
                mma16816(oac[mt][nt], ph_[mt], c0, c1);
            }
    }

    #pragma unroll
    for (int mt = 0; mt < 2; ++mt)
        #pragma unroll
        for (int half = 0; half < 2; ++half) {
            int i = wm2 * 32 + mt * 16 + (lane >> 2) + half * 8;
            __nv_bfloat16* prow = g_oc + (size_t)(bw * 64 + i) * 2048;
            #pragma unroll
            for (int nt = 0; nt < 2; ++nt) {
                int d = wn4 * 16 + nt * 8 + (lane & 3) * 2;
                float x0 = oac[mt][nt][half * 2 + 0];
                float x1 = oac[mt][nt][half * 2 + 1];
                __nv_bfloat16 h0 = __float2bfloat16(x0);
                __nv_bfloat16 h1 = __float2bfloat16(x1);
                __nv_bfloat16 l0 = __float2bfloat16(x0 - __bfloat162float(h0));
                __nv_bfloat16 l1 = __float2bfloat16(x1 - __bfloat162float(h1));
                int cc = hd * 64 + d;
                int blk = cc >> 5, w = cc & 31;
                __nv_bfloat162 hh; hh.x = h0; hh.y = h1;
                __nv_bfloat162 ll; ll.x = l0; ll.y = l1;
                *(__nv_bfloat162*)(prow + blk * 64 + w)      = hh;
                *(__nv_bfloat162*)(prow + blk * 64 + w + 32) = ll;
            }
        }
}

// ---------------- launch ------------------------------------------------------
extern "C" void kernel_launch(void* const* d_in, const int* in_sizes, int n_in,
                              void* d_out, int out_size) {
    const float* x   = (const float*)d_in[0];
    const float* Wq  = (const float*)d_in[1];
    const float* Wk  = (const float*)d_in[2];
    const float* Wv  = (const float*)d_in[3];
    const float* bv  = (const float*)d_in[4];
    const float* Wo  = (const float*)d_in[5];
    const float* bo  = (const float*)d_in[6];
    const float* ls  = (const float*)d_in[7];
    const float* w1  = (const float*)d_in[8];
    const float* b1  = (const float*)d_in[9];
    const float* w2  = (const float*)d_in[10];
    float* out = (float*)d_out;

    cudaFuncSetAttribute(mma_gemm, cudaFuncAttributeMaxDynamicSharedMemorySize, DYN_SMEM);
    cudaFuncSetAttribute(attn_kernel, cudaFuncAttributeMaxDynamicSharedMemorySize, ATT_SMEM);

    // fused prologue: conv_x (16384) + conv_w (4096) + cpb (225)
    fused_pre<<<20705, 256>>>(x, Wq, Wk, Wv, Wo, w1, b1, w2);

    __nv_bfloat16* xc = nullptr;
    __nv_bfloat16* oc = nullptr;
    __nv_bfloat16* wc = nullptr;
    cudaGetSymbolAddress((void**)&xc, g_xc);
    cudaGetSymbolAddress((void**)&oc, g_oc);
    cudaGetSymbolAddress((void**)&wc, g_wc);

    // QKV: A = g_xc [32768 x 2048], B = g_wc mats 0-2 (N = 3072)
    mma_gemm<<<dim3(24, 256), 256, DYN_SMEM>>>(xc, wc, bv, nullptr, 0);
    attn_kernel<<<8192, 256, ATT_SMEM>>>(ls);
    // OUT: A = g_oc, B = g_wc mat 3 (N = 1024)
    mma_gemm<<<dim3(8, 256), 256, DYN_SMEM>>>(oc, wc + (size_t)3 * 1024 * 2048, bo, out, 1);
}